// round 4
// baseline (speedup 1.0000x reference)
#include <cuda_runtime.h>
#include <cuda_bf16.h>
#include <float.h>

#define EPS 1e-6f

// Problem dims
#define M_ROWS 16384   // B*T
#define DIM    512
#define K_CEN  4096
#define DO     1024

// -------- scratch (device globals; no cudaMalloc allowed) --------
__device__ float g_CW[K_CEN * DO];   // centers @ W + b   (16 MB)
__device__ float g_c2[K_CEN];
__device__ int   g_sel[M_ROWS];

typedef unsigned long long ull;

__device__ __forceinline__ ull pack2(float x, float y) {
    ull r;
    asm("mov.b64 %0, {%1, %2};" : "=l"(r) : "f"(x), "f"(y));
    return r;
}
__device__ __forceinline__ void fma2(ull& d, ull a, ull b) {
    asm("fma.rn.f32x2 %0, %1, %2, %0;" : "+l"(d) : "l"(a), "l"(b));
}
__device__ __forceinline__ void unpack2(ull v, float& x, float& y) {
    asm("mov.b64 {%0, %1}, %2;" : "=f"(x), "=f"(y) : "l"(v));
}

// ================= kernel 1: c2[k] = sum(centers[k]^2) =================
// grid 512, block 256 (8 warps), one warp per center
__global__ void k1_c2(const float* __restrict__ centers, float* __restrict__ c2) {
    int w = threadIdx.x >> 5;
    int lane = threadIdx.x & 31;
    int c = blockIdx.x * 8 + w;
    const float* row = centers + (size_t)c * DIM;
    float s = 0.f;
#pragma unroll
    for (int r = 0; r < 4; ++r) {
        float4 v = *(const float4*)(row + lane * 4 + r * 128);
        s += v.x * v.x + v.y * v.y + v.z * v.z + v.w * v.w;
    }
#pragma unroll
    for (int o = 16; o > 0; o >>= 1) s += __shfl_xor_sync(0xffffffff, s, o);
    if (lane == 0) c2[c] = s;
}

// ================= kernel 2: CW = centers @ W + b =================
// BM=64, BN=64, BK=16, 256 threads, 4x4 per thread
__global__ void k2_cw(const float* __restrict__ centers, const float* __restrict__ W,
                      const float* __restrict__ b, float* __restrict__ CW) {
    __shared__ float As[16][68];  // As[k][m]
    __shared__ float Bs[16][68];  // Bs[k][n]
    const int tid = threadIdx.x;
    const int tx = tid & 15, ty = tid >> 4;
    const int n0 = blockIdx.x * 64;
    const int m0 = blockIdx.y * 64;

    float acc[4][4] = {};

    for (int kt = 0; kt < DIM / 16; ++kt) {
        // A tile 64x16
        {
            int m = tid >> 2, k4 = tid & 3;
            float4 v = *(const float4*)(centers + (size_t)(m0 + m) * DIM + kt * 16 + k4 * 4);
            As[k4 * 4 + 0][m] = v.x;
            As[k4 * 4 + 1][m] = v.y;
            As[k4 * 4 + 2][m] = v.z;
            As[k4 * 4 + 3][m] = v.w;
        }
        // B tile 16x64
        {
            int k = tid >> 4, n4 = tid & 15;
            float4 v = *(const float4*)(W + (size_t)(kt * 16 + k) * DO + n0 + n4 * 4);
            *(float4*)&Bs[k][n4 * 4] = v;
        }
        __syncthreads();
#pragma unroll
        for (int kk = 0; kk < 16; ++kk) {
            float4 a4 = *(const float4*)&As[kk][ty * 4];
            float4 b4 = *(const float4*)&Bs[kk][tx * 4];
            float av[4] = {a4.x, a4.y, a4.z, a4.w};
            float bv[4] = {b4.x, b4.y, b4.z, b4.w};
#pragma unroll
            for (int i = 0; i < 4; ++i)
#pragma unroll
                for (int j = 0; j < 4; ++j) acc[i][j] = fmaf(av[i], bv[j], acc[i][j]);
        }
        __syncthreads();
    }
#pragma unroll
    for (int i = 0; i < 4; ++i) {
        float4 o;
        int n = n0 + tx * 4;
        o.x = acc[i][0] + __ldg(b + n + 0);
        o.y = acc[i][1] + __ldg(b + n + 1);
        o.z = acc[i][2] + __ldg(b + n + 2);
        o.w = acc[i][3] + __ldg(b + n + 3);
        *(float4*)(CW + (size_t)(m0 + ty * 4 + i) * DO + n) = o;
    }
}

// ================= kernel 3: fused distance GEMM + argmin =================
// score(r,k) = c2[k] - 2*(x[r]+eps)·centers[k]   (x2 dropped: row-constant)
// grid 256 (64 rows each), 256 threads (16x16), 4 rows x 4 cols per thread,
// FFMA2 packed mainloop. x-slab [64][512] resident in SMEM.
#define XS_PITCH 516
#define BS_PITCH 68
__global__ void __launch_bounds__(256, 1)
k3_argmin(const float* __restrict__ x, const float* __restrict__ centers,
          const float* __restrict__ c2, int* __restrict__ sel) {
    extern __shared__ float smem[];
    float* Xs = smem;                         // 64 * 516
    float* Bs = Xs + 64 * XS_PITCH;           // 32 * 68
    float* redf = Bs + 32 * BS_PITCH;         // 256 * 4
    int* redi = (int*)(redf + 256 * 4);       // 256 * 4

    const int tid = threadIdx.x;
    const int tx = tid & 15, ty = tid >> 4;
    const int m0 = blockIdx.x * 64;

    // load x slab (+EPS)
    for (int f = tid; f < 64 * 128; f += 256) {
        int row = f >> 7, c4 = f & 127;
        float4 v = *(const float4*)(x + (size_t)(m0 + row) * DIM + c4 * 4);
        v.x += EPS; v.y += EPS; v.z += EPS; v.w += EPS;
        *(float4*)(Xs + row * XS_PITCH + c4 * 4) = v;
    }
    __syncthreads();

    float best[4] = {FLT_MAX, FLT_MAX, FLT_MAX, FLT_MAX};
    int bidx[4] = {0, 0, 0, 0};

    for (int ct = 0; ct < K_CEN / 64; ++ct) {
        ull acc2[4][2];
#pragma unroll
        for (int i = 0; i < 4; ++i) { acc2[i][0] = 0ull; acc2[i][1] = 0ull; }
        const float* cbase = centers + (size_t)ct * 64 * DIM;

        for (int kt = 0; kt < DIM / 32; ++kt) {
            __syncthreads();
            // stage centers tile [64 c][32 k] transposed -> Bs[k][c]
#pragma unroll
            for (int r = 0; r < 2; ++r) {
                int f = tid + r * 256;
                int c = f >> 3, k4 = f & 7;
                float4 v = *(const float4*)(cbase + (size_t)c * DIM + kt * 32 + k4 * 4);
                float* dst = &Bs[(k4 * 4) * BS_PITCH + c];
                dst[0 * BS_PITCH] = v.x;
                dst[1 * BS_PITCH] = v.y;
                dst[2 * BS_PITCH] = v.z;
                dst[3 * BS_PITCH] = v.w;
            }
            __syncthreads();
#pragma unroll
            for (int kq = 0; kq < 8; ++kq) {
                float4 a4[4];
#pragma unroll
                for (int i = 0; i < 4; ++i)
                    a4[i] = *(const float4*)(Xs + (ty * 4 + i) * XS_PITCH + kt * 32 + kq * 4);
#pragma unroll
                for (int u = 0; u < 4; ++u) {
                    int kk = kq * 4 + u;
                    ull b01 = *(const ull*)(Bs + kk * BS_PITCH + tx * 4);
                    ull b23 = *(const ull*)(Bs + kk * BS_PITCH + tx * 4 + 2);
                    float av0 = (u == 0) ? a4[0].x : (u == 1) ? a4[0].y : (u == 2) ? a4[0].z : a4[0].w;
                    float av1 = (u == 0) ? a4[1].x : (u == 1) ? a4[1].y : (u == 2) ? a4[1].z : a4[1].w;
                    float av2 = (u == 0) ? a4[2].x : (u == 1) ? a4[2].y : (u == 2) ? a4[2].z : a4[2].w;
                    float av3 = (u == 0) ? a4[3].x : (u == 1) ? a4[3].y : (u == 2) ? a4[3].z : a4[3].w;
                    ull aa0 = pack2(av0, av0);
                    ull aa1 = pack2(av1, av1);
                    ull aa2 = pack2(av2, av2);
                    ull aa3 = pack2(av3, av3);
                    fma2(acc2[0][0], aa0, b01); fma2(acc2[0][1], aa0, b23);
                    fma2(acc2[1][0], aa1, b01); fma2(acc2[1][1], aa1, b23);
                    fma2(acc2[2][0], aa2, b01); fma2(acc2[2][1], aa2, b23);
                    fma2(acc2[3][0], aa3, b01); fma2(acc2[3][1], aa3, b23);
                }
            }
        }
        // scores + running argmin (strict < keeps first occurrence)
        int colbase = ct * 64 + tx * 4;
        float c2v0 = __ldg(c2 + colbase + 0);
        float c2v1 = __ldg(c2 + colbase + 1);
        float c2v2 = __ldg(c2 + colbase + 2);
        float c2v3 = __ldg(c2 + colbase + 3);
#pragma unroll
        for (int i = 0; i < 4; ++i) {
            float d0, d1, d2, d3;
            unpack2(acc2[i][0], d0, d1);
            unpack2(acc2[i][1], d2, d3);
            float s0 = fmaf(-2.f, d0, c2v0);
            float s1 = fmaf(-2.f, d1, c2v1);
            float s2 = fmaf(-2.f, d2, c2v2);
            float s3 = fmaf(-2.f, d3, c2v3);
            if (s0 < best[i]) { best[i] = s0; bidx[i] = colbase + 0; }
            if (s1 < best[i]) { best[i] = s1; bidx[i] = colbase + 1; }
            if (s2 < best[i]) { best[i] = s2; bidx[i] = colbase + 2; }
            if (s3 < best[i]) { best[i] = s3; bidx[i] = colbase + 3; }
        }
    }

    // cross-tx reduction (threads sharing the same rows)
    __syncthreads();
#pragma unroll
    for (int i = 0; i < 4; ++i) {
        redf[tid * 4 + i] = best[i];
        redi[tid * 4 + i] = bidx[i];
    }
    __syncthreads();
    if (tx == 0) {
#pragma unroll
        for (int i = 0; i < 4; ++i) {
            float bs = redf[(ty * 16) * 4 + i];
            int bi = redi[(ty * 16) * 4 + i];
            for (int t = 1; t < 16; ++t) {
                float s = redf[(ty * 16 + t) * 4 + i];
                int ix = redi[(ty * 16 + t) * 4 + i];
                if (s < bs || (s == bs && ix < bi)) { bs = s; bi = ix; }
            }
            sel[m0 + ty * 4 + i] = bi;
        }
    }
}

// ================= kernel 4: out[r,:] = CW[sel[r],:] =================
__global__ void k4_gather(const int* __restrict__ sel, const float* __restrict__ CW,
                          float* __restrict__ out) {
    int r = blockIdx.x;
    int s = __ldg(sel + r);
    float4 v = *(const float4*)(CW + (size_t)s * DO + threadIdx.x * 4);
    *(float4*)(out + (size_t)r * DO + threadIdx.x * 4) = v;
}

// ================= launch =================
#define SMEM3 ((64 * XS_PITCH + 32 * BS_PITCH + 256 * 4) * 4 + 256 * 4 * 4)

extern "C" void kernel_launch(void* const* d_in, const int* in_sizes, int n_in,
                              void* d_out, int out_size) {
    const float* x = (const float*)d_in[0];
    const float* centers = (const float*)d_in[1];
    const float* W = (const float*)d_in[2];
    const float* b = (const float*)d_in[3];
    float* out = (float*)d_out;

    float* CW; cudaGetSymbolAddress((void**)&CW, g_CW);
    float* c2; cudaGetSymbolAddress((void**)&c2, g_c2);
    int* sel;  cudaGetSymbolAddress((void**)&sel, g_sel);

    cudaFuncSetAttribute(k3_argmin, cudaFuncAttributeMaxDynamicSharedMemorySize, SMEM3);

    k1_c2<<<K_CEN / 8, 256>>>(centers, c2);
    k2_cw<<<dim3(DO / 64, K_CEN / 64), 256>>>(centers, W, b, CW);
    k3_argmin<<<M_ROWS / 64, 256, SMEM3>>>(x, centers, c2, sel);
    k4_gather<<<M_ROWS, 256>>>(sel, CW, out);
}

// round 5
// speedup vs baseline: 1.0012x; 1.0012x over previous
#include <cuda_runtime.h>
#include <cuda_bf16.h>
#include <float.h>

#define EPS 1e-6f

// Problem dims
#define M_ROWS 16384   // B*T
#define DIM    512
#define K_CEN  4096
#define DO     1024

// -------- scratch (device globals; no cudaMalloc allowed) --------
__device__ float g_CW[K_CEN * DO];   // centers @ W + b   (16 MB)
__device__ float g_c2[K_CEN];
__device__ int   g_sel[M_ROWS];

typedef unsigned long long ull;

__device__ __forceinline__ ull pack2(float x, float y) {
    ull r;
    asm("mov.b64 %0, {%1, %2};" : "=l"(r) : "f"(x), "f"(y));
    return r;
}
__device__ __forceinline__ void fma2(ull& d, ull a, ull b) {
    asm("fma.rn.f32x2 %0, %1, %2, %0;" : "+l"(d) : "l"(a), "l"(b));
}
__device__ __forceinline__ void unpack2(ull v, float& x, float& y) {
    asm("mov.b64 {%0, %1}, %2;" : "=f"(x), "=f"(y) : "l"(v));
}

// ================= kernel 1: c2[k] = sum(centers[k]^2) =================
// grid 512, block 256 (8 warps), one warp per center
__global__ void k1_c2(const float* __restrict__ centers, float* __restrict__ c2) {
    int w = threadIdx.x >> 5;
    int lane = threadIdx.x & 31;
    int c = blockIdx.x * 8 + w;
    const float* row = centers + (size_t)c * DIM;
    float s = 0.f;
#pragma unroll
    for (int r = 0; r < 4; ++r) {
        float4 v = *(const float4*)(row + lane * 4 + r * 128);
        s += v.x * v.x + v.y * v.y + v.z * v.z + v.w * v.w;
    }
#pragma unroll
    for (int o = 16; o > 0; o >>= 1) s += __shfl_xor_sync(0xffffffff, s, o);
    if (lane == 0) c2[c] = s;
}

// ================= kernel 2: CW = centers @ W + b =================
// BM=64, BN=64, BK=16, 256 threads, 4x4 per thread
__global__ void k2_cw(const float* __restrict__ centers, const float* __restrict__ W,
                      const float* __restrict__ b, float* __restrict__ CW) {
    __shared__ float As[16][68];  // As[k][m]
    __shared__ float Bs[16][68];  // Bs[k][n]
    const int tid = threadIdx.x;
    const int tx = tid & 15, ty = tid >> 4;
    const int n0 = blockIdx.x * 64;
    const int m0 = blockIdx.y * 64;

    float acc[4][4] = {};

    for (int kt = 0; kt < DIM / 16; ++kt) {
        // A tile 64x16
        {
            int m = tid >> 2, k4 = tid & 3;
            float4 v = *(const float4*)(centers + (size_t)(m0 + m) * DIM + kt * 16 + k4 * 4);
            As[k4 * 4 + 0][m] = v.x;
            As[k4 * 4 + 1][m] = v.y;
            As[k4 * 4 + 2][m] = v.z;
            As[k4 * 4 + 3][m] = v.w;
        }
        // B tile 16x64
        {
            int k = tid >> 4, n4 = tid & 15;
            float4 v = *(const float4*)(W + (size_t)(kt * 16 + k) * DO + n0 + n4 * 4);
            *(float4*)&Bs[k][n4 * 4] = v;
        }
        __syncthreads();
#pragma unroll
        for (int kk = 0; kk < 16; ++kk) {
            float4 a4 = *(const float4*)&As[kk][ty * 4];
            float4 b4 = *(const float4*)&Bs[kk][tx * 4];
            float av[4] = {a4.x, a4.y, a4.z, a4.w};
            float bv[4] = {b4.x, b4.y, b4.z, b4.w};
#pragma unroll
            for (int i = 0; i < 4; ++i)
#pragma unroll
                for (int j = 0; j < 4; ++j) acc[i][j] = fmaf(av[i], bv[j], acc[i][j]);
        }
        __syncthreads();
    }
#pragma unroll
    for (int i = 0; i < 4; ++i) {
        float4 o;
        int n = n0 + tx * 4;
        o.x = acc[i][0] + __ldg(b + n + 0);
        o.y = acc[i][1] + __ldg(b + n + 1);
        o.z = acc[i][2] + __ldg(b + n + 2);
        o.w = acc[i][3] + __ldg(b + n + 3);
        *(float4*)(CW + (size_t)(m0 + ty * 4 + i) * DO + n) = o;
    }
}

// ================= kernel 3: fused distance GEMM + argmin =================
// score(r,k) = c2[k] - 2*(x[r]+eps)·centers[k]   (x2 dropped: row-constant)
// grid 256 (64 rows each), 256 threads (16x16), 4 rows x 4 cols per thread,
// FFMA2 packed mainloop. x-slab [64][512] resident in SMEM.
#define XS_PITCH 516
#define BS_PITCH 68
__global__ void __launch_bounds__(256, 1)
k3_argmin(const float* __restrict__ x, const float* __restrict__ centers,
          const float* __restrict__ c2, int* __restrict__ sel) {
    extern __shared__ float smem[];
    float* Xs = smem;                         // 64 * 516
    float* Bs = Xs + 64 * XS_PITCH;           // 32 * 68
    float* redf = Bs + 32 * BS_PITCH;         // 256 * 4
    int* redi = (int*)(redf + 256 * 4);       // 256 * 4

    const int tid = threadIdx.x;
    const int tx = tid & 15, ty = tid >> 4;
    const int m0 = blockIdx.x * 64;

    // load x slab (+EPS)
    for (int f = tid; f < 64 * 128; f += 256) {
        int row = f >> 7, c4 = f & 127;
        float4 v = *(const float4*)(x + (size_t)(m0 + row) * DIM + c4 * 4);
        v.x += EPS; v.y += EPS; v.z += EPS; v.w += EPS;
        *(float4*)(Xs + row * XS_PITCH + c4 * 4) = v;
    }
    __syncthreads();

    float best[4] = {FLT_MAX, FLT_MAX, FLT_MAX, FLT_MAX};
    int bidx[4] = {0, 0, 0, 0};

    for (int ct = 0; ct < K_CEN / 64; ++ct) {
        ull acc2[4][2];
#pragma unroll
        for (int i = 0; i < 4; ++i) { acc2[i][0] = 0ull; acc2[i][1] = 0ull; }
        const float* cbase = centers + (size_t)ct * 64 * DIM;

        for (int kt = 0; kt < DIM / 32; ++kt) {
            __syncthreads();
            // stage centers tile [64 c][32 k] transposed -> Bs[k][c]
#pragma unroll
            for (int r = 0; r < 2; ++r) {
                int f = tid + r * 256;
                int c = f >> 3, k4 = f & 7;
                float4 v = *(const float4*)(cbase + (size_t)c * DIM + kt * 32 + k4 * 4);
                float* dst = &Bs[(k4 * 4) * BS_PITCH + c];
                dst[0 * BS_PITCH] = v.x;
                dst[1 * BS_PITCH] = v.y;
                dst[2 * BS_PITCH] = v.z;
                dst[3 * BS_PITCH] = v.w;
            }
            __syncthreads();
#pragma unroll
            for (int kq = 0; kq < 8; ++kq) {
                float4 a4[4];
#pragma unroll
                for (int i = 0; i < 4; ++i)
                    a4[i] = *(const float4*)(Xs + (ty * 4 + i) * XS_PITCH + kt * 32 + kq * 4);
#pragma unroll
                for (int u = 0; u < 4; ++u) {
                    int kk = kq * 4 + u;
                    ull b01 = *(const ull*)(Bs + kk * BS_PITCH + tx * 4);
                    ull b23 = *(const ull*)(Bs + kk * BS_PITCH + tx * 4 + 2);
                    float av0 = (u == 0) ? a4[0].x : (u == 1) ? a4[0].y : (u == 2) ? a4[0].z : a4[0].w;
                    float av1 = (u == 0) ? a4[1].x : (u == 1) ? a4[1].y : (u == 2) ? a4[1].z : a4[1].w;
                    float av2 = (u == 0) ? a4[2].x : (u == 1) ? a4[2].y : (u == 2) ? a4[2].z : a4[2].w;
                    float av3 = (u == 0) ? a4[3].x : (u == 1) ? a4[3].y : (u == 2) ? a4[3].z : a4[3].w;
                    ull aa0 = pack2(av0, av0);
                    ull aa1 = pack2(av1, av1);
                    ull aa2 = pack2(av2, av2);
                    ull aa3 = pack2(av3, av3);
                    fma2(acc2[0][0], aa0, b01); fma2(acc2[0][1], aa0, b23);
                    fma2(acc2[1][0], aa1, b01); fma2(acc2[1][1], aa1, b23);
                    fma2(acc2[2][0], aa2, b01); fma2(acc2[2][1], aa2, b23);
                    fma2(acc2[3][0], aa3, b01); fma2(acc2[3][1], aa3, b23);
                }
            }
        }
        // scores + running argmin (strict < keeps first occurrence)
        int colbase = ct * 64 + tx * 4;
        float c2v0 = __ldg(c2 + colbase + 0);
        float c2v1 = __ldg(c2 + colbase + 1);
        float c2v2 = __ldg(c2 + colbase + 2);
        float c2v3 = __ldg(c2 + colbase + 3);
#pragma unroll
        for (int i = 0; i < 4; ++i) {
            float d0, d1, d2, d3;
            unpack2(acc2[i][0], d0, d1);
            unpack2(acc2[i][1], d2, d3);
            float s0 = fmaf(-2.f, d0, c2v0);
            float s1 = fmaf(-2.f, d1, c2v1);
            float s2 = fmaf(-2.f, d2, c2v2);
            float s3 = fmaf(-2.f, d3, c2v3);
            if (s0 < best[i]) { best[i] = s0; bidx[i] = colbase + 0; }
            if (s1 < best[i]) { best[i] = s1; bidx[i] = colbase + 1; }
            if (s2 < best[i]) { best[i] = s2; bidx[i] = colbase + 2; }
            if (s3 < best[i]) { best[i] = s3; bidx[i] = colbase + 3; }
        }
    }

    // cross-tx reduction (threads sharing the same rows)
    __syncthreads();
#pragma unroll
    for (int i = 0; i < 4; ++i) {
        redf[tid * 4 + i] = best[i];
        redi[tid * 4 + i] = bidx[i];
    }
    __syncthreads();
    if (tx == 0) {
#pragma unroll
        for (int i = 0; i < 4; ++i) {
            float bs = redf[(ty * 16) * 4 + i];
            int bi = redi[(ty * 16) * 4 + i];
            for (int t = 1; t < 16; ++t) {
                float s = redf[(ty * 16 + t) * 4 + i];
                int ix = redi[(ty * 16 + t) * 4 + i];
                if (s < bs || (s == bs && ix < bi)) { bs = s; bi = ix; }
            }
            sel[m0 + ty * 4 + i] = bi;
        }
    }
}

// ================= kernel 4: out[r,:] = CW[sel[r],:] =================
__global__ void k4_gather(const int* __restrict__ sel, const float* __restrict__ CW,
                          float* __restrict__ out) {
    int r = blockIdx.x;
    int s = __ldg(sel + r);
    float4 v = *(const float4*)(CW + (size_t)s * DO + threadIdx.x * 4);
    *(float4*)(out + (size_t)r * DO + threadIdx.x * 4) = v;
}

// ================= launch =================
#define SMEM3 ((64 * XS_PITCH + 32 * BS_PITCH + 256 * 4) * 4 + 256 * 4 * 4)

extern "C" void kernel_launch(void* const* d_in, const int* in_sizes, int n_in,
                              void* d_out, int out_size) {
    const float* x = (const float*)d_in[0];
    const float* centers = (const float*)d_in[1];
    const float* W = (const float*)d_in[2];
    const float* b = (const float*)d_in[3];
    float* out = (float*)d_out;

    float* CW; cudaGetSymbolAddress((void**)&CW, g_CW);
    float* c2; cudaGetSymbolAddress((void**)&c2, g_c2);
    int* sel;  cudaGetSymbolAddress((void**)&sel, g_sel);

    cudaFuncSetAttribute(k3_argmin, cudaFuncAttributeMaxDynamicSharedMemorySize, SMEM3);

    k1_c2<<<K_CEN / 8, 256>>>(centers, c2);
    k2_cw<<<dim3(DO / 64, K_CEN / 64), 256>>>(centers, W, b, CW);
    k3_argmin<<<M_ROWS / 64, 256, SMEM3>>>(x, centers, c2, sel);
    k4_gather<<<M_ROWS, 256>>>(sel, CW, out);
}

// round 7
// speedup vs baseline: 1.5785x; 1.5767x over previous
#include <cuda_runtime.h>
#include <cuda_bf16.h>
#include <float.h>
#include <stdint.h>

#define EPS 1e-6f

// Problem dims
#define M_ROWS 16384   // B*T
#define DIM    512
#define K_CEN  4096
#define DO     1024

// k3 tiling
#define BM 128
#define BN 128
#define NT (K_CEN / BN)        // 32 n-tiles
#define KITERS (DIM / 64)      // 8 k-chunks of 64 bf16
#define OFF_AH 0u
#define OFF_AL 16384u
#define OFF_BH 32768u
#define OFF_BL 49152u
#define STAGE_BYTES 65536
#define SM_C2 0
#define SM_EB 512
#define SM_STAGE0 9216
#define SMEM_K3 (SM_STAGE0 + 2 * STAGE_BYTES)
#define TAU 0.03f

// -------- scratch (device globals; no cudaMalloc allowed) --------
__device__ float g_CW[K_CEN * DO];
__device__ float g_c2[K_CEN];
__device__ int   g_sel[M_ROWS];
__device__ int   g_flags[M_ROWS];
__device__ __align__(16) __nv_bfloat16 g_Xh[M_ROWS * DIM];
__device__ __align__(16) __nv_bfloat16 g_Xl[M_ROWS * DIM];
__device__ __align__(16) __nv_bfloat16 g_Ch[K_CEN * DIM];
__device__ __align__(16) __nv_bfloat16 g_Cl[K_CEN * DIM];
__device__ unsigned long long g_part[M_ROWS * 2 * NT];   // per (row, ntile) top-2 keys

typedef unsigned long long ull;

// ---------------- helpers ----------------
__device__ __forceinline__ uint32_t smem_u32(const void* p) {
    uint32_t a;
    asm("{ .reg .u64 t; cvta.to.shared.u64 t, %1; cvt.u32.u64 %0, t; }" : "=r"(a) : "l"(p));
    return a;
}
__device__ __forceinline__ uint32_t sw128(uint32_t b) { return b ^ ((b >> 3) & 0x70); }

__device__ __forceinline__ uint32_t fkey(float s) {
    uint32_t b = __float_as_uint(s);
    return (b & 0x80000000u) ? ~b : (b | 0x80000000u);
}
__device__ __forceinline__ float unkey(uint32_t k) {
    uint32_t b = (k & 0x80000000u) ? (k ^ 0x80000000u) : ~k;
    return __uint_as_float(b);
}

#define LDMX4(r, addr) \
    asm volatile("ldmatrix.sync.aligned.m8n8.x4.shared.b16 {%0,%1,%2,%3}, [%4];" \
        : "=r"((r)[0]), "=r"((r)[1]), "=r"((r)[2]), "=r"((r)[3]) : "r"(addr))

__device__ __forceinline__ void mma_bf16(float* d, const uint32_t* a, uint32_t b0, uint32_t b1) {
    asm volatile("mma.sync.aligned.m16n8k16.row.col.f32.bf16.bf16.f32 "
        "{%0,%1,%2,%3}, {%4,%5,%6,%7}, {%8,%9}, {%0,%1,%2,%3};"
        : "+f"(d[0]), "+f"(d[1]), "+f"(d[2]), "+f"(d[3])
        : "r"(a[0]), "r"(a[1]), "r"(a[2]), "r"(a[3]), "r"(b0), "r"(b1));
}

__device__ __forceinline__ void merge2(ull& a1, ull& a2, ull b1, ull b2) {
    ull lo = (a1 < b1) ? a1 : b1;
    ull hi = (a1 < b1) ? b1 : a1;
    ull m  = (a2 < b2) ? a2 : b2;
    a1 = lo;
    a2 = (hi < m) ? hi : m;
}

// ================= kernel 0: fp32 -> bf16 (hi, lo) split =================
__global__ void k0_split(const float* __restrict__ src, __nv_bfloat16* __restrict__ hi,
                         __nv_bfloat16* __restrict__ lo, int n, float eps) {
    int i = (blockIdx.x * blockDim.x + threadIdx.x) * 4;
    if (i >= n) return;
    float4 v = *(const float4*)(src + i);
    float a0 = v.x + eps, a1 = v.y + eps, a2 = v.z + eps, a3 = v.w + eps;
    __nv_bfloat16 h0 = __float2bfloat16_rn(a0), h1 = __float2bfloat16_rn(a1);
    __nv_bfloat16 h2 = __float2bfloat16_rn(a2), h3 = __float2bfloat16_rn(a3);
    __nv_bfloat16 l0 = __float2bfloat16_rn(a0 - __bfloat162float(h0));
    __nv_bfloat16 l1 = __float2bfloat16_rn(a1 - __bfloat162float(h1));
    __nv_bfloat16 l2 = __float2bfloat16_rn(a2 - __bfloat162float(h2));
    __nv_bfloat16 l3 = __float2bfloat16_rn(a3 - __bfloat162float(h3));
    ushort4 hv = make_ushort4(__bfloat16_as_ushort(h0), __bfloat16_as_ushort(h1),
                              __bfloat16_as_ushort(h2), __bfloat16_as_ushort(h3));
    ushort4 lv = make_ushort4(__bfloat16_as_ushort(l0), __bfloat16_as_ushort(l1),
                              __bfloat16_as_ushort(l2), __bfloat16_as_ushort(l3));
    *(ushort4*)((unsigned short*)hi + i) = hv;
    *(ushort4*)((unsigned short*)lo + i) = lv;
}

// ================= kernel 1: c2[k] = sum(centers[k]^2) =================
__global__ void k1_c2(const float* __restrict__ centers, float* __restrict__ c2) {
    int w = threadIdx.x >> 5;
    int lane = threadIdx.x & 31;
    int c = blockIdx.x * 8 + w;
    const float* row = centers + (size_t)c * DIM;
    float s = 0.f;
#pragma unroll
    for (int r = 0; r < 4; ++r) {
        float4 v = *(const float4*)(row + lane * 4 + r * 128);
        s += v.x * v.x + v.y * v.y + v.z * v.z + v.w * v.w;
    }
#pragma unroll
    for (int o = 16; o > 0; o >>= 1) s += __shfl_xor_sync(0xffffffff, s, o);
    if (lane == 0) c2[c] = s;
}

// ================= kernel 2: CW = centers @ W + b (fp32) =================
__global__ void k2_cw(const float* __restrict__ centers, const float* __restrict__ W,
                      const float* __restrict__ b, float* __restrict__ CW) {
    __shared__ float As[16][68];
    __shared__ float Bs[16][68];
    const int tid = threadIdx.x;
    const int tx = tid & 15, ty = tid >> 4;
    const int n0 = blockIdx.x * 64;
    const int m0 = blockIdx.y * 64;
    float acc[4][4] = {};
    for (int kt = 0; kt < DIM / 16; ++kt) {
        {
            int m = tid >> 2, k4 = tid & 3;
            float4 v = *(const float4*)(centers + (size_t)(m0 + m) * DIM + kt * 16 + k4 * 4);
            As[k4 * 4 + 0][m] = v.x; As[k4 * 4 + 1][m] = v.y;
            As[k4 * 4 + 2][m] = v.z; As[k4 * 4 + 3][m] = v.w;
        }
        {
            int k = tid >> 4, n4 = tid & 15;
            float4 v = *(const float4*)(W + (size_t)(kt * 16 + k) * DO + n0 + n4 * 4);
            *(float4*)&Bs[k][n4 * 4] = v;
        }
        __syncthreads();
#pragma unroll
        for (int kk = 0; kk < 16; ++kk) {
            float4 a4 = *(const float4*)&As[kk][ty * 4];
            float4 b4 = *(const float4*)&Bs[kk][tx * 4];
            float av[4] = {a4.x, a4.y, a4.z, a4.w};
            float bv[4] = {b4.x, b4.y, b4.z, b4.w};
#pragma unroll
            for (int i = 0; i < 4; ++i)
#pragma unroll
                for (int j = 0; j < 4; ++j) acc[i][j] = fmaf(av[i], bv[j], acc[i][j]);
        }
        __syncthreads();
    }
#pragma unroll
    for (int i = 0; i < 4; ++i) {
        float4 o;
        int n = n0 + tx * 4;
        o.x = acc[i][0] + __ldg(b + n + 0);
        o.y = acc[i][1] + __ldg(b + n + 1);
        o.z = acc[i][2] + __ldg(b + n + 2);
        o.w = acc[i][3] + __ldg(b + n + 3);
        *(float4*)(CW + (size_t)(m0 + ty * 4 + i) * DO + n) = o;
    }
}

// ================= kernel 3: HMMA bf16x3 distance GEMM + per-tile top2 =================
__device__ __forceinline__ void load_stage(uint32_t smb, int s, int kt, int m0, int n0,
                                           const __nv_bfloat16* Xh, const __nv_bfloat16* Xl,
                                           const __nv_bfloat16* Ch, const __nv_bfloat16* Cl,
                                           int tid) {
    uint32_t base = smb + SM_STAGE0 + (uint32_t)s * STAGE_BYTES;
#pragma unroll
    for (int i = 0; i < 16; ++i) {
        int f = tid + i * 256;
        int sec = f >> 10;             // 0:Ah 1:Al 2:Bh 3:Bl
        int row = (f >> 3) & 127;
        int c = f & 7;
        const __nv_bfloat16* src;
        if (sec == 0)      src = Xh + (size_t)(m0 + row) * DIM + kt * 64 + c * 8;
        else if (sec == 1) src = Xl + (size_t)(m0 + row) * DIM + kt * 64 + c * 8;
        else if (sec == 2) src = Ch + (size_t)(n0 + row) * DIM + kt * 64 + c * 8;
        else               src = Cl + (size_t)(n0 + row) * DIM + kt * 64 + c * 8;
        uint32_t dst = base + (uint32_t)sec * 16384u + sw128((uint32_t)(row * 128 + c * 16));
        asm volatile("cp.async.cg.shared.global [%0], [%1], 16;" :: "r"(dst), "l"(src));
    }
}

__global__ void __launch_bounds__(256, 1)
k3_mma(const __nv_bfloat16* __restrict__ Xh, const __nv_bfloat16* __restrict__ Xl,
       const __nv_bfloat16* __restrict__ Ch, const __nv_bfloat16* __restrict__ Cl,
       const float* __restrict__ c2, ull* __restrict__ part) {
    extern __shared__ char smem[];
    uint32_t smb = smem_u32(smem);
    float* c2s = (float*)(smem + SM_C2);
    ull* eb = (ull*)(smem + SM_EB);

    const int tid = threadIdx.x;
    const int wid = tid >> 5;
    const int l = tid & 31;
    const int wm = wid >> 2;          // 0..1 -> 64 rows each
    const int wn = wid & 3;           // 0..3 -> 32 cols each
    const int m0 = blockIdx.y * BM;
    const int n0 = blockIdx.x * BN;

    if (tid < 128) c2s[tid] = __ldg(c2 + n0 + tid);

    float acc[4][4][4];
#pragma unroll
    for (int a = 0; a < 4; ++a)
#pragma unroll
        for (int b = 0; b < 4; ++b)
#pragma unroll
            for (int c = 0; c < 4; ++c) acc[a][b][c] = 0.f;

    load_stage(smb, 0, 0, m0, n0, Xh, Xl, Ch, Cl, tid);
    asm volatile("cp.async.commit_group;" ::: "memory");

    const uint32_t arow = (uint32_t)(wm * 64 + (l & 15));
    const uint32_t brow = (uint32_t)(wn * 32 + (l & 15));
    const uint32_t kb = (uint32_t)((l >> 4) << 4);

    for (int it = 0; it < KITERS; ++it) {
        int cur = it & 1;
        if (it + 1 < KITERS) {
            load_stage(smb, cur ^ 1, it + 1, m0, n0, Xh, Xl, Ch, Cl, tid);
            asm volatile("cp.async.commit_group;" ::: "memory");
            asm volatile("cp.async.wait_group 1;" ::: "memory");
        } else {
            asm volatile("cp.async.wait_group 0;" ::: "memory");
        }
        __syncthreads();

        uint32_t sA = smb + SM_STAGE0 + (uint32_t)cur * STAGE_BYTES;
        uint32_t sB = sA + OFF_BH;
#pragma unroll
        for (int ks = 0; ks < 4; ++ks) {
            uint32_t col = (uint32_t)(ks * 32) + kb;
            uint32_t ah[4][4], al[4][4], bh[2][4], bl[2][4];
#pragma unroll
            for (int mt = 0; mt < 4; ++mt) {
                uint32_t off = sw128((arow + mt * 16) * 128 + col);
                LDMX4(ah[mt], sA + OFF_AH + off);
                LDMX4(al[mt], sA + OFF_AL + off);
            }
#pragma unroll
            for (int bt = 0; bt < 2; ++bt) {
                uint32_t off = sw128((brow + bt * 16) * 128 + col);
                LDMX4(bh[bt], sB + off);
                LDMX4(bl[bt], sB + 16384u + off);
            }
#pragma unroll
            for (int mt = 0; mt < 4; ++mt)
#pragma unroll
                for (int nt = 0; nt < 4; ++nt) {
                    int bt = nt >> 1, ns = nt & 1;
                    mma_bf16(acc[mt][nt], ah[mt], bh[bt][ns], bh[bt][ns + 2]);  // hh
                    mma_bf16(acc[mt][nt], ah[mt], bl[bt][ns], bl[bt][ns + 2]);  // hl
                    mma_bf16(acc[mt][nt], al[mt], bh[bt][ns], bh[bt][ns + 2]);  // lh
                }
        }
        __syncthreads();
    }

    // ---- epilogue: scores + top2 per row ----
    ull t1[8], t2[8];
#pragma unroll
    for (int mt = 0; mt < 4; ++mt)
#pragma unroll
        for (int h = 0; h < 2; ++h) {
            int slot = mt * 2 + h;
            ull k1 = ~0ull, k2 = ~0ull;
#pragma unroll
            for (int nt = 0; nt < 4; ++nt)
#pragma unroll
                for (int e = 0; e < 2; ++e) {
                    int nl = wn * 32 + nt * 8 + (l & 3) * 2 + e;
                    float s = c2s[nl] - 2.f * acc[mt][nt][h * 2 + e];
                    ull key = ((ull)fkey(s) << 32) | (unsigned)(n0 + nl);
                    if (key < k1) { k2 = k1; k1 = key; }
                    else if (key < k2) { k2 = key; }
                }
            t1[slot] = k1; t2[slot] = k2;
        }
#pragma unroll
    for (int o = 1; o <= 2; o <<= 1)
#pragma unroll
        for (int s = 0; s < 8; ++s) {
            ull o1 = __shfl_xor_sync(0xffffffff, t1[s], o);
            ull o2 = __shfl_xor_sync(0xffffffff, t2[s], o);
            merge2(t1[s], t2[s], o1, o2);
        }
    if ((l & 3) == 0) {
#pragma unroll
        for (int mt = 0; mt < 4; ++mt)
#pragma unroll
            for (int h = 0; h < 2; ++h) {
                int rloc = wm * 64 + mt * 16 + h * 8 + (l >> 2);
                eb[(rloc * 4 + wn) * 2 + 0] = t1[mt * 2 + h];
                eb[(rloc * 4 + wn) * 2 + 1] = t2[mt * 2 + h];
            }
    }
    __syncthreads();
    if (tid < 128) {
        ull a1 = eb[(tid * 4 + 0) * 2], a2 = eb[(tid * 4 + 0) * 2 + 1];
#pragma unroll
        for (int w = 1; w < 4; ++w)
            merge2(a1, a2, eb[(tid * 4 + w) * 2], eb[(tid * 4 + w) * 2 + 1]);
        part[(size_t)(m0 + tid) * (2 * NT) + blockIdx.x * 2 + 0] = a1;
        part[(size_t)(m0 + tid) * (2 * NT) + blockIdx.x * 2 + 1] = a2;
    }
}

// ================= kernel 3b: global top-2 reduce + margin flag =================
__global__ void k3b_reduce(const ull* __restrict__ part, int* __restrict__ sel,
                           int* __restrict__ flags) {
    int row = blockIdx.x * 8 + (threadIdx.x >> 5);
    int lane = threadIdx.x & 31;
    ull a = part[(size_t)row * 64 + lane];
    ull b = part[(size_t)row * 64 + 32 + lane];
    ull m1 = (a < b) ? a : b;
    ull m2 = (a < b) ? b : a;
#pragma unroll
    for (int o = 16; o > 0; o >>= 1) {
        ull o1 = __shfl_xor_sync(0xffffffff, m1, o);
        ull o2 = __shfl_xor_sync(0xffffffff, m2, o);
        merge2(m1, m2, o1, o2);
    }
    if (lane == 0) {
        float s1 = unkey((uint32_t)(m1 >> 32));
        float s2 = unkey((uint32_t)(m2 >> 32));
        sel[row] = (int)(m1 & 0xFFFFFFFFull);
        flags[row] = (s2 - s1 < TAU) ? 1 : 0;
    }
}

// ================= kernel 3c: exact fp32 rescore for flagged rows =================
__global__ void k3c_exact(const float* __restrict__ x, const float* __restrict__ centers,
                          const float* __restrict__ c2, const int* __restrict__ flags,
                          int* __restrict__ sel) {
    int r = blockIdx.x;
    if (!__ldg(flags + r)) return;
    __shared__ float xs[DIM];
    __shared__ ull red[8];
    int tid = threadIdx.x;
    for (int i = tid; i < DIM / 4; i += 256) {
        float4 v = *(const float4*)(x + (size_t)r * DIM + i * 4);
        v.x += EPS; v.y += EPS; v.z += EPS; v.w += EPS;
        *(float4*)(xs + i * 4) = v;
    }
    __syncthreads();
    ull best = ~0ull;
#pragma unroll 1
    for (int j = 0; j < 16; ++j) {
        int k = tid * 16 + j;
        const float* c = centers + (size_t)k * DIM;
        float dot = 0.f;
#pragma unroll
        for (int d = 0; d < DIM; d += 4) {
            float4 cv = *(const float4*)(c + d);
            dot = fmaf(xs[d + 0], cv.x, dot);
            dot = fmaf(xs[d + 1], cv.y, dot);
            dot = fmaf(xs[d + 2], cv.z, dot);
            dot = fmaf(xs[d + 3], cv.w, dot);
        }
        float s = __ldg(c2 + k) - 2.f * dot;
        ull key = ((ull)fkey(s) << 32) | (unsigned)k;
        if (key < best) best = key;
    }
#pragma unroll
    for (int o = 16; o > 0; o >>= 1) {
        ull ov = __shfl_xor_sync(0xffffffff, best, o);
        if (ov < best) best = ov;
    }
    if ((tid & 31) == 0) red[tid >> 5] = best;
    __syncthreads();
    if (tid == 0) {
        ull b = red[0];
#pragma unroll
        for (int w = 1; w < 8; ++w)
            if (red[w] < b) b = red[w];
        sel[r] = (int)(b & 0xFFFFFFFFull);
    }
}

// ================= kernel 4: out[r,:] = CW[sel[r],:] =================
__global__ void k4_gather(const int* __restrict__ sel, const float* __restrict__ CW,
                          float* __restrict__ out) {
    int r = blockIdx.x;
    int s = __ldg(sel + r);
    float4 v = *(const float4*)(CW + (size_t)s * DO + threadIdx.x * 4);
    *(float4*)(out + (size_t)r * DO + threadIdx.x * 4) = v;
}

// ================= launch =================
extern "C" void kernel_launch(void* const* d_in, const int* in_sizes, int n_in,
                              void* d_out, int out_size) {
    const float* x = (const float*)d_in[0];
    const float* centers = (const float*)d_in[1];
    const float* W = (const float*)d_in[2];
    const float* b = (const float*)d_in[3];
    float* out = (float*)d_out;

    float* CW;  cudaGetSymbolAddress((void**)&CW, g_CW);
    float* c2;  cudaGetSymbolAddress((void**)&c2, g_c2);
    int* sel;   cudaGetSymbolAddress((void**)&sel, g_sel);
    int* flags; cudaGetSymbolAddress((void**)&flags, g_flags);
    __nv_bfloat16 *Xh, *Xl, *Ch, *Cl;
    cudaGetSymbolAddress((void**)&Xh, g_Xh);
    cudaGetSymbolAddress((void**)&Xl, g_Xl);
    cudaGetSymbolAddress((void**)&Ch, g_Ch);
    cudaGetSymbolAddress((void**)&Cl, g_Cl);
    ull* part; cudaGetSymbolAddress((void**)&part, g_part);

    static bool attr_set = false;
    if (!attr_set) {
        cudaFuncSetAttribute(k3_mma, cudaFuncAttributeMaxDynamicSharedMemorySize, SMEM_K3);
        attr_set = true;
    }

    k0_split<<<(M_ROWS * DIM / 4 + 255) / 256, 256>>>(x, Xh, Xl, M_ROWS * DIM, EPS);
    k0_split<<<(K_CEN * DIM / 4 + 255) / 256, 256>>>(centers, Ch, Cl, K_CEN * DIM, 0.f);
    k1_c2<<<K_CEN / 8, 256>>>(centers, c2);
    k2_cw<<<dim3(DO / 64, K_CEN / 64), 256>>>(centers, W, b, CW);
    k3_mma<<<dim3(NT, M_ROWS / BM), 256, SMEM_K3>>>(Xh, Xl, Ch, Cl, c2, part);
    k3b_reduce<<<M_ROWS / 8, 256>>>(part, sel, flags);
    k3c_exact<<<M_ROWS, 256>>>(x, centers, c2, flags, sel);
    k4_gather<<<M_ROWS, 256>>>(sel, CW, out);
}

// round 11
// speedup vs baseline: 6.1633x; 3.9045x over previous
#include <cuda_runtime.h>
#include <cuda_bf16.h>
#include <cuda_fp16.h>
#include <float.h>
#include <stdint.h>

#define EPS 1e-6f

// Problem dims
#define M_ROWS 16384   // B*T
#define DIM    512
#define K_CEN  4096
#define DO     1024

// k3 tiling
#define BM 128
#define BN 128
#define NT (K_CEN / BN)        // 32 n-tiles
#define KITERS (DIM / 64)      // 8 k-chunks of 64 fp16
#define OFF_BH 16384u
#define STAGE_BYTES 32768
#define SM_C2 0
#define SM_EB 512
#define SM_STAGE0 9216
#define SMEM_K3 (SM_STAGE0 + 2 * STAGE_BYTES)
#define TAU 0.10f

// -------- scratch (device globals; no cudaMalloc allowed) --------
__device__ float g_CW[K_CEN * DO];
__device__ float g_c2[K_CEN];
__device__ int   g_sel[M_ROWS];
__device__ int   g_flags[M_ROWS];
__device__ __align__(16) __half g_Xh[M_ROWS * DIM];
__device__ __align__(16) __half g_Ch[K_CEN * DIM];
__device__ unsigned long long g_part[M_ROWS * 2 * NT];   // per (row, ntile) top-2 keys

typedef unsigned long long ull;

// ---------------- helpers ----------------
__device__ __forceinline__ uint32_t smem_u32(const void* p) {
    uint32_t a;
    asm("{ .reg .u64 t; cvta.to.shared.u64 t, %1; cvt.u32.u64 %0, t; }" : "=r"(a) : "l"(p));
    return a;
}
__device__ __forceinline__ uint32_t sw128(uint32_t b) { return b ^ ((b >> 3) & 0x70); }

__device__ __forceinline__ uint32_t fkey(float s) {
    uint32_t b = __float_as_uint(s);
    return (b & 0x80000000u) ? ~b : (b | 0x80000000u);
}
__device__ __forceinline__ float unkey(uint32_t k) {
    uint32_t b = (k & 0x80000000u) ? (k ^ 0x80000000u) : ~k;
    return __uint_as_float(b);
}

#define LDMX4(r, addr) \
    asm volatile("ldmatrix.sync.aligned.m8n8.x4.shared.b16 {%0,%1,%2,%3}, [%4];" \
        : "=r"((r)[0]), "=r"((r)[1]), "=r"((r)[2]), "=r"((r)[3]) : "r"(addr))

__device__ __forceinline__ void mma_fp16(float* d, const uint32_t* a, uint32_t b0, uint32_t b1) {
    asm volatile("mma.sync.aligned.m16n8k16.row.col.f32.f16.f16.f32 "
        "{%0,%1,%2,%3}, {%4,%5,%6,%7}, {%8,%9}, {%0,%1,%2,%3};"
        : "+f"(d[0]), "+f"(d[1]), "+f"(d[2]), "+f"(d[3])
        : "r"(a[0]), "r"(a[1]), "r"(a[2]), "r"(a[3]), "r"(b0), "r"(b1));
}

__device__ __forceinline__ void merge2(ull& a1, ull& a2, ull b1, ull b2) {
    ull lo = (a1 < b1) ? a1 : b1;
    ull hi = (a1 < b1) ? b1 : a1;
    ull m  = (a2 < b2) ? a2 : b2;
    a1 = lo;
    a2 = (hi < m) ? hi : m;
}

// ================= kernel 0: fp32 -> fp16 convert (+eps) =================
__global__ void k0_half(const float* __restrict__ src, __half* __restrict__ dst,
                        int n, float eps) {
    int i = (blockIdx.x * blockDim.x + threadIdx.x) * 4;
    if (i >= n) return;
    float4 v = *(const float4*)(src + i);
    __half2 h0 = __floats2half2_rn(v.x + eps, v.y + eps);
    __half2 h1 = __floats2half2_rn(v.z + eps, v.w + eps);
    uint2 pk;
    pk.x = *(uint32_t*)&h0;
    pk.y = *(uint32_t*)&h1;
    *(uint2*)((__half*)dst + i) = pk;
}

// ================= kernel 1: c2[k] = sum(centers[k]^2) =================
__global__ void k1_c2(const float* __restrict__ centers, float* __restrict__ c2) {
    int w = threadIdx.x >> 5;
    int lane = threadIdx.x & 31;
    int c = blockIdx.x * 8 + w;
    const float* row = centers + (size_t)c * DIM;
    float s = 0.f;
#pragma unroll
    for (int r = 0; r < 4; ++r) {
        float4 v = *(const float4*)(row + lane * 4 + r * 128);
        s += v.x * v.x + v.y * v.y + v.z * v.z + v.w * v.w;
    }
#pragma unroll
    for (int o = 16; o > 0; o >>= 1) s += __shfl_xor_sync(0xffffffff, s, o);
    if (lane == 0) c2[c] = s;
}

// ================= kernel 2: CW = centers @ W + b (fp32) =================
__global__ void k2_cw(const float* __restrict__ centers, const float* __restrict__ W,
                      const float* __restrict__ b, float* __restrict__ CW) {
    __shared__ float As[16][68];
    __shared__ float Bs[16][68];
    const int tid = threadIdx.x;
    const int tx = tid & 15, ty = tid >> 4;
    const int n0 = blockIdx.x * 64;
    const int m0 = blockIdx.y * 64;
    float acc[4][4] = {};
    for (int kt = 0; kt < DIM / 16; ++kt) {
        {
            int m = tid >> 2, k4 = tid & 3;
            float4 v = *(const float4*)(centers + (size_t)(m0 + m) * DIM + kt * 16 + k4 * 4);
            As[k4 * 4 + 0][m] = v.x; As[k4 * 4 + 1][m] = v.y;
            As[k4 * 4 + 2][m] = v.z; As[k4 * 4 + 3][m] = v.w;
        }
        {
            int k = tid >> 4, n4 = tid & 15;
            float4 v = *(const float4*)(W + (size_t)(kt * 16 + k) * DO + n0 + n4 * 4);
            *(float4*)&Bs[k][n4 * 4] = v;
        }
        __syncthreads();
#pragma unroll
        for (int kk = 0; kk < 16; ++kk) {
            float4 a4 = *(const float4*)&As[kk][ty * 4];
            float4 b4 = *(const float4*)&Bs[kk][tx * 4];
            float av[4] = {a4.x, a4.y, a4.z, a4.w};
            float bv[4] = {b4.x, b4.y, b4.z, b4.w};
#pragma unroll
            for (int i = 0; i < 4; ++i)
#pragma unroll
                for (int j = 0; j < 4; ++j) acc[i][j] = fmaf(av[i], bv[j], acc[i][j]);
        }
        __syncthreads();
    }
#pragma unroll
    for (int i = 0; i < 4; ++i) {
        float4 o;
        int n = n0 + tx * 4;
        o.x = acc[i][0] + __ldg(b + n + 0);
        o.y = acc[i][1] + __ldg(b + n + 1);
        o.z = acc[i][2] + __ldg(b + n + 2);
        o.w = acc[i][3] + __ldg(b + n + 3);
        *(float4*)(CW + (size_t)(m0 + ty * 4 + i) * DO + n) = o;
    }
}

// ================= kernel 3: fp16 HMMA distance GEMM + per-tile top2 =================
__device__ __forceinline__ void load_stage(uint32_t smb, int s, int kt, int m0, int n0,
                                           const __half* Xh, const __half* Ch, int tid) {
    uint32_t base = smb + SM_STAGE0 + (uint32_t)s * STAGE_BYTES;
#pragma unroll
    for (int i = 0; i < 8; ++i) {
        int f = tid + i * 256;
        int sec = f >> 10;             // 0:A 1:B
        int row = (f >> 3) & 127;
        int c = f & 7;
        const __half* src = (sec == 0)
            ? Xh + (size_t)(m0 + row) * DIM + kt * 64 + c * 8
            : Ch + (size_t)(n0 + row) * DIM + kt * 64 + c * 8;
        uint32_t dst = base + (uint32_t)sec * 16384u + sw128((uint32_t)(row * 128 + c * 16));
        asm volatile("cp.async.cg.shared.global [%0], [%1], 16;" :: "r"(dst), "l"(src));
    }
}

__global__ void __launch_bounds__(256, 2)
k3_mma(const __half* __restrict__ Xh, const __half* __restrict__ Ch,
       const float* __restrict__ c2, ull* __restrict__ part) {
    extern __shared__ char smem[];
    uint32_t smb = smem_u32(smem);
    float* c2s = (float*)(smem + SM_C2);
    ull* eb = (ull*)(smem + SM_EB);

    const int tid = threadIdx.x;
    const int wid = tid >> 5;
    const int l = tid & 31;
    const int wm = wid >> 2;          // 0..1 -> 64 rows each
    const int wn = wid & 3;           // 0..3 -> 32 cols each
    const int m0 = blockIdx.y * BM;
    const int n0 = blockIdx.x * BN;

    if (tid < 128) c2s[tid] = __ldg(c2 + n0 + tid);

    float acc[4][4][4];
#pragma unroll
    for (int a = 0; a < 4; ++a)
#pragma unroll
        for (int b = 0; b < 4; ++b)
#pragma unroll
            for (int c = 0; c < 4; ++c) acc[a][b][c] = 0.f;

    load_stage(smb, 0, 0, m0, n0, Xh, Ch, tid);
    asm volatile("cp.async.commit_group;" ::: "memory");

    const uint32_t arow = (uint32_t)(wm * 64 + (l & 15));
    const uint32_t brow = (uint32_t)(wn * 32 + (l & 15));
    const uint32_t kb = (uint32_t)((l >> 4) << 4);

    for (int it = 0; it < KITERS; ++it) {
        int cur = it & 1;
        if (it + 1 < KITERS) {
            load_stage(smb, cur ^ 1, it + 1, m0, n0, Xh, Ch, tid);
            asm volatile("cp.async.commit_group;" ::: "memory");
            asm volatile("cp.async.wait_group 1;" ::: "memory");
        } else {
            asm volatile("cp.async.wait_group 0;" ::: "memory");
        }
        __syncthreads();

        uint32_t sA = smb + SM_STAGE0 + (uint32_t)cur * STAGE_BYTES;
        uint32_t sB = sA + OFF_BH;
#pragma unroll
        for (int ks = 0; ks < 4; ++ks) {
            uint32_t col = (uint32_t)(ks * 32) + kb;
            uint32_t ah[4][4], bh[2][4];
#pragma unroll
            for (int mt = 0; mt < 4; ++mt) {
                uint32_t off = sw128((arow + mt * 16) * 128 + col);
                LDMX4(ah[mt], sA + off);
            }
#pragma unroll
            for (int bt = 0; bt < 2; ++bt) {
                uint32_t off = sw128((brow + bt * 16) * 128 + col);
                LDMX4(bh[bt], sB + off);
            }
#pragma unroll
            for (int mt = 0; mt < 4; ++mt)
#pragma unroll
                for (int nt = 0; nt < 4; ++nt) {
                    int bt = nt >> 1, ns = nt & 1;
                    mma_fp16(acc[mt][nt], ah[mt], bh[bt][ns], bh[bt][ns + 2]);
                }
        }
        __syncthreads();
    }

    // ---- epilogue: scores + top2 per row ----
    ull t1[8], t2[8];
#pragma unroll
    for (int mt = 0; mt < 4; ++mt)
#pragma unroll
        for (int h = 0; h < 2; ++h) {
            int slot = mt * 2 + h;
            ull k1 = ~0ull, k2 = ~0ull;
#pragma unroll
            for (int nt = 0; nt < 4; ++nt)
#pragma unroll
                for (int e = 0; e < 2; ++e) {
                    int nl = wn * 32 + nt * 8 + (l & 3) * 2 + e;
                    float s = c2s[nl] - 2.f * acc[mt][nt][h * 2 + e];
                    ull key = ((ull)fkey(s) << 32) | (unsigned)(n0 + nl);
                    if (key < k1) { k2 = k1; k1 = key; }
                    else if (key < k2) { k2 = key; }
                }
            t1[slot] = k1; t2[slot] = k2;
        }
#pragma unroll
    for (int o = 1; o <= 2; o <<= 1)
#pragma unroll
        for (int s = 0; s < 8; ++s) {
            ull o1 = __shfl_xor_sync(0xffffffff, t1[s], o);
            ull o2 = __shfl_xor_sync(0xffffffff, t2[s], o);
            merge2(t1[s], t2[s], o1, o2);
        }
    if ((l & 3) == 0) {
#pragma unroll
        for (int mt = 0; mt < 4; ++mt)
#pragma unroll
            for (int h = 0; h < 2; ++h) {
                int rloc = wm * 64 + mt * 16 + h * 8 + (l >> 2);
                eb[(rloc * 4 + wn) * 2 + 0] = t1[mt * 2 + h];
                eb[(rloc * 4 + wn) * 2 + 1] = t2[mt * 2 + h];
            }
    }
    __syncthreads();
    if (tid < 128) {
        ull a1 = eb[(tid * 4 + 0) * 2], a2 = eb[(tid * 4 + 0) * 2 + 1];
#pragma unroll
        for (int w = 1; w < 4; ++w)
            merge2(a1, a2, eb[(tid * 4 + w) * 2], eb[(tid * 4 + w) * 2 + 1]);
        part[(size_t)(m0 + tid) * (2 * NT) + blockIdx.x * 2 + 0] = a1;
        part[(size_t)(m0 + tid) * (2 * NT) + blockIdx.x * 2 + 1] = a2;
    }
}

// ================= kernel 3b: global top-2 reduce + margin flag =================
__global__ void k3b_reduce(const ull* __restrict__ part, int* __restrict__ sel,
                           int* __restrict__ flags) {
    int row = blockIdx.x * 8 + (threadIdx.x >> 5);
    int lane = threadIdx.x & 31;
    ull a = part[(size_t)row * 64 + lane];
    ull b = part[(size_t)row * 64 + 32 + lane];
    ull m1 = (a < b) ? a : b;
    ull m2 = (a < b) ? b : a;
#pragma unroll
    for (int o = 16; o > 0; o >>= 1) {
        ull o1 = __shfl_xor_sync(0xffffffff, m1, o);
        ull o2 = __shfl_xor_sync(0xffffffff, m2, o);
        merge2(m1, m2, o1, o2);
    }
    if (lane == 0) {
        float s1 = unkey((uint32_t)(m1 >> 32));
        float s2 = unkey((uint32_t)(m2 >> 32));
        sel[row] = (int)(m1 & 0xFFFFFFFFull);
        flags[row] = (s2 - s1 < TAU) ? 1 : 0;
    }
}

// ================= kernel 3c: exact fp32 rescore of the 64 candidates =================
__global__ void k3c_cand(const float* __restrict__ x, const float* __restrict__ centers,
                         const float* __restrict__ c2, const int* __restrict__ flags,
                         const ull* __restrict__ part, int* __restrict__ sel) {
    int r = blockIdx.x;
    if (!__ldg(flags + r)) return;
    __shared__ float xs[DIM];
    __shared__ ull red[8];
    int tid = threadIdx.x;
    int w = tid >> 5, lane = tid & 31;
    for (int i = tid; i < DIM / 4; i += 256) {
        float4 v = *(const float4*)(x + (size_t)r * DIM + i * 4);
        v.x += EPS; v.y += EPS; v.z += EPS; v.w += EPS;
        *(float4*)(xs + i * 4) = v;
    }
    __syncthreads();
    ull best = ~0ull;
#pragma unroll 1
    for (int j = w; j < 64; j += 8) {
        int k = (int)(part[(size_t)r * 64 + j] & 0xFFFFFFFFull);
        const float* c = centers + (size_t)k * DIM;
        float dot = 0.f;
#pragma unroll
        for (int d = 0; d < 4; ++d) {
            float4 cv = __ldg((const float4*)(c + lane * 4 + d * 128));
            float4 xv = *(const float4*)(xs + lane * 4 + d * 128);
            dot = fmaf(xv.x, cv.x, dot);
            dot = fmaf(xv.y, cv.y, dot);
            dot = fmaf(xv.z, cv.z, dot);
            dot = fmaf(xv.w, cv.w, dot);
        }
#pragma unroll
        for (int o = 16; o > 0; o >>= 1) dot += __shfl_xor_sync(0xffffffff, dot, o);
        float s = __ldg(c2 + k) - 2.f * dot;
        ull key = ((ull)fkey(s) << 32) | (unsigned)k;
        if (key < best) best = key;
    }
    if (lane == 0) red[w] = best;
    __syncthreads();
    if (tid == 0) {
        ull b = red[0];
#pragma unroll
        for (int i = 1; i < 8; ++i)
            if (red[i] < b) b = red[i];
        sel[r] = (int)(b & 0xFFFFFFFFull);
    }
}

// ================= kernel 4: out[r,:] = CW[sel[r],:] =================
__global__ void k4_gather(const int* __restrict__ sel, const float* __restrict__ CW,
                          float* __restrict__ out) {
    int r = blockIdx.x;
    int s = __ldg(sel + r);
    float4 v = *(const float4*)(CW + (size_t)s * DO + threadIdx.x * 4);
    *(float4*)(out + (size_t)r * DO + threadIdx.x * 4) = v;
}

// ================= launch =================
extern "C" void kernel_launch(void* const* d_in, const int* in_sizes, int n_in,
                              void* d_out, int out_size) {
    const float* x = (const float*)d_in[0];
    const float* centers = (const float*)d_in[1];
    const float* W = (const float*)d_in[2];
    const float* b = (const float*)d_in[3];
    float* out = (float*)d_out;

    float* CW;  cudaGetSymbolAddress((void**)&CW, g_CW);
    float* c2;  cudaGetSymbolAddress((void**)&c2, g_c2);
    int* sel;   cudaGetSymbolAddress((void**)&sel, g_sel);
    int* flags; cudaGetSymbolAddress((void**)&flags, g_flags);
    __half *Xh, *Ch;
    cudaGetSymbolAddress((void**)&Xh, g_Xh);
    cudaGetSymbolAddress((void**)&Ch, g_Ch);
    ull* part; cudaGetSymbolAddress((void**)&part, g_part);

    static bool attr_set = false;
    if (!attr_set) {
        cudaFuncSetAttribute(k3_mma, cudaFuncAttributeMaxDynamicSharedMemorySize, SMEM_K3);
        attr_set = true;
    }

    k0_half<<<(M_ROWS * DIM / 4 + 255) / 256, 256>>>(x, Xh, M_ROWS * DIM, EPS);
    k0_half<<<(K_CEN * DIM / 4 + 255) / 256, 256>>>(centers, Ch, K_CEN * DIM, 0.f);
    k1_c2<<<K_CEN / 8, 256>>>(centers, c2);
    k2_cw<<<dim3(DO / 64, K_CEN / 64), 256>>>(centers, W, b, CW);
    k3_mma<<<dim3(NT, M_ROWS / BM), 256, SMEM_K3>>>(Xh, Ch, c2, part);
    k3b_reduce<<<M_ROWS / 8, 256>>>(part, sel, flags);
    k3c_cand<<<M_ROWS, 256>>>(x, centers, c2, flags, part, sel);
    k4_gather<<<M_ROWS, 256>>>(sel, CW, out);
}